// round 1
// baseline (speedup 1.0000x reference)
#include <cuda_runtime.h>

// ExponentialUnitNorm: state_t = 0.01*|x_t| + 0.99*state_{t-1}; out = x/sqrt(state)
// x: [B=16, C=1, T=2000, F=481, 2] fp32. One thread per (b,f) chain, serial over t.
// Unroll U=40 so 40 independent LDG.64s are batched per thread for DRAM MLP.

#define B_DIM 16
#define T_DIM 2000
#define F_DIM 481
#define FPAD  512
#define UNR   40

__global__ __launch_bounds__(64, 1)
void eun_kernel(const float2* __restrict__ x,
                const float* __restrict__ init_state,
                float2* __restrict__ out) {
    int gid = blockIdx.x * 64 + threadIdx.x;
    int b = gid >> 9;          // / FPAD
    int f = gid & (FPAD - 1);  // % FPAD
    if (f >= F_DIM) return;

    const float2* __restrict__ in = x   + (size_t)b * T_DIM * F_DIM + f;
    float2* __restrict__       o  = out + (size_t)b * T_DIM * F_DIM + f;

    float s = init_state[f];
    const float AL = 0.99f;
    const float BE = 1.0f - AL;

    #pragma unroll 1
    for (int it = 0; it < T_DIM / UNR; ++it) {
        float2 v[UNR];
        // Batch of independent loads — front-batched by ptxas for MLP.
        #pragma unroll
        for (int u = 0; u < UNR; ++u) {
            v[u] = __ldg(in + (size_t)u * F_DIM);
        }
        in += (size_t)UNR * F_DIM;

        #pragma unroll
        for (int u = 0; u < UNR; ++u) {
            float m2 = fmaf(v[u].x, v[u].x, v[u].y * v[u].y);
            m2 = fmaxf(m2, 1e-14f);
            float m;
            asm("sqrt.approx.f32 %0, %1;" : "=f"(m) : "f"(m2));
            s = fmaf(BE, m, AL * s);   // serial scan chain (4-cyc FMA dep per step)
            float r;
            asm("rsqrt.approx.f32 %0, %1;" : "=f"(r) : "f"(s));
            float2 w;
            w.x = v[u].x * r;
            w.y = v[u].y * r;
            o[(size_t)u * F_DIM] = w;
        }
        o += (size_t)UNR * F_DIM;
    }
}

extern "C" void kernel_launch(void* const* d_in, const int* in_sizes, int n_in,
                              void* d_out, int out_size) {
    const float2* x = (const float2*)d_in[0];          // [16,1,2000,481,2] fp32
    const float*  init_state = (const float*)d_in[1];  // [1,1,481,1] fp32
    float2* out = (float2*)d_out;

    dim3 block(64);
    dim3 grid((B_DIM * FPAD) / 64);  // 128 blocks
    eun_kernel<<<grid, block>>>(x, init_state, out);
}

// round 2
// speedup vs baseline: 1.7759x; 1.7759x over previous
#include <cuda_runtime.h>

// ExponentialUnitNorm via exact block-local chunked linear-scan composition.
// x: [B=16, C=1, T=2000, F=481, 2] fp32.
// Recurrence s_t = BE*m_t + AL*s_{t-1} is linear: a chunk of length L maps
// s_in -> A*s_in + Bsum with A = AL^L. Split T into NCH=8 chunks of TC=250,
// compose inside one block via smem. Exact (up to fp rounding), no global sync.
//
// Block: 256 threads = 32 f-lanes x 8 chunk-rows. Grid: 16 b x 16 f-tiles = 256.

#define B_DIM 16
#define T_DIM 2000
#define F_DIM 481
#define NCH   8
#define TC    250   // NCH*TC = T_DIM
#define UNR   10
#define ALPHA_F 0.99f
#define BETA_F  0.01f

__global__ __launch_bounds__(256, 4)
void eun_kernel(const float2* __restrict__ x,
                const float* __restrict__ init_state,
                float2* __restrict__ out) {
    __shared__ float Bs[NCH][32];
    __shared__ float Ss[NCH][32];

    const int tid   = threadIdx.x;
    const int lane  = tid & 31;
    const int chunk = tid >> 5;                 // 0..7
    const int ftile = blockIdx.x & 15;          // 16 tiles of 32 f (covers 512 >= 481)
    const int b     = blockIdx.x >> 4;          // 0..15
    const int f     = ftile * 32 + lane;
    const bool act  = (f < F_DIM);

    const size_t base = (size_t)b * T_DIM * F_DIM + (size_t)chunk * TC * F_DIM + f;
    const float2* __restrict__ in = x + base;

    // ---- Phase 1: per-chunk linear aggregate B (zero-init state) ----
    float Bacc = 0.0f;
    if (act) {
        #pragma unroll 1
        for (int it = 0; it < TC / UNR; ++it) {
            float2 v[UNR];
            #pragma unroll
            for (int u = 0; u < UNR; ++u)
                v[u] = __ldg(in + (size_t)(it * UNR + u) * F_DIM);
            #pragma unroll
            for (int u = 0; u < UNR; ++u) {
                float m2 = fmaf(v[u].x, v[u].x, v[u].y * v[u].y);
                m2 = fmaxf(m2, 1e-14f);
                float m;
                asm("sqrt.approx.f32 %0, %1;" : "=f"(m) : "f"(m2));
                Bacc = fmaf(ALPHA_F, Bacc, BETA_F * m);
            }
        }
    }
    Bs[chunk][lane] = Bacc;
    __syncthreads();

    // ---- Phase 2: compose chunk start-states (warp 0, one thread per f-lane) ----
    if (tid < 32) {
        // A = 0.99^250 computed exactly in double (repeated squaring)
        double p = 1.0, sq = 0.99;
        int e = TC;
        while (e) { if (e & 1) p *= sq; sq *= sq; e >>= 1; }
        const float A = (float)p;

        float s = act ? init_state[f] : 0.0f;
        #pragma unroll
        for (int c = 0; c < NCH; ++c) {
            Ss[c][lane] = s;                    // state entering chunk c
            s = fmaf(A, s, Bs[c][lane]);
        }
    }
    __syncthreads();

    // ---- Phase 3: replay chunk from known start state, write output ----
    float s = Ss[chunk][lane];
    float2* __restrict__ o = out + base;
    if (act) {
        #pragma unroll 1
        for (int it = 0; it < TC / UNR; ++it) {
            float2 v[UNR];
            #pragma unroll
            for (int u = 0; u < UNR; ++u)
                v[u] = __ldg(in + (size_t)(it * UNR + u) * F_DIM);
            #pragma unroll
            for (int u = 0; u < UNR; ++u) {
                float m2 = fmaf(v[u].x, v[u].x, v[u].y * v[u].y);
                m2 = fmaxf(m2, 1e-14f);
                float m;
                asm("sqrt.approx.f32 %0, %1;" : "=f"(m) : "f"(m2));
                s = fmaf(BETA_F, m, ALPHA_F * s);
                float r;
                asm("rsqrt.approx.f32 %0, %1;" : "=f"(r) : "f"(s));
                float2 w;
                w.x = v[u].x * r;
                w.y = v[u].y * r;
                o[(size_t)(it * UNR + u) * F_DIM] = w;
            }
        }
    }
}

extern "C" void kernel_launch(void* const* d_in, const int* in_sizes, int n_in,
                              void* d_out, int out_size) {
    const float2* x = (const float2*)d_in[0];          // [16,1,2000,481,2] fp32
    const float*  init_state = (const float*)d_in[1];  // [1,1,481,1] fp32
    float2* out = (float2*)d_out;

    dim3 block(256);
    dim3 grid(B_DIM * 16);   // 256 blocks
    eun_kernel<<<grid, block>>>(x, init_state, out);
}

// round 4
// speedup vs baseline: 1.9495x; 1.0978x over previous
#include <cuda_runtime.h>

// ExponentialUnitNorm, exact segmented chunked linear-scan.
// x: [B=16, C=1, T=2000, F=481, 2] fp32.
// s_t = 0.01*m_t + 0.99*s_{t-1}. Linear: chunk of length L maps s -> A*s + B, A=0.99^L.
// Loop over NSEG=10 segments of 200 steps; inside a segment, 8 chunks x 25 steps
// are processed in parallel by the 8 warp-rows of the block and composed in smem.
// The phase-3 replay re-reads data the block read microseconds earlier -> L2 hit,
// so DRAM traffic is the compulsory 246 MB instead of 369 MB.
//
// Block: 256 threads = 32 f-lanes x 8 chunk-rows. Grid: 16 b x 16 f-tiles = 256.

#define B_DIM 16
#define T_DIM 2000
#define F_DIM 481
#define NSEG  10
#define CH    8
#define TCK   25                 // SEG = CH*TCK = 200, NSEG*SEG = T_DIM
#define SEG   (CH * TCK)
#define ALPHA_F 0.99f
#define BETA_F  0.01f

__global__ __launch_bounds__(256, 3)
void eun_kernel(const float2* __restrict__ x,
                const float* __restrict__ init_state,
                float2* __restrict__ out) {
    __shared__ float Bs[CH][32];
    __shared__ float Ss[CH][32];

    const int tid   = threadIdx.x;
    const int lane  = tid & 31;
    const int chunk = tid >> 5;                 // 0..7
    const int ftile = blockIdx.x & 15;
    const int b     = blockIdx.x >> 4;
    const int f     = ftile * 32 + lane;
    const bool act  = (f < F_DIM);

    // A = 0.99^TCK exactly, via repeated squaring in double (warp 0 uses it).
    float A;
    {
        double p = 1.0, sq = 0.99; int e = TCK;
        while (e) { if (e & 1) p *= sq; sq *= sq; e >>= 1; }
        A = (float)p;
    }

    // Running state for this chain, carried in warp 0's registers.
    float scarry = (tid < 32 && act) ? init_state[f] : 0.0f;

    #pragma unroll 1
    for (int seg = 0; seg < NSEG; ++seg) {
        const size_t base = ((size_t)b * T_DIM + (size_t)seg * SEG + chunk * TCK) * F_DIM + f;
        const float2* __restrict__ in = x + base;

        // ---- Phase 1: per-chunk linear aggregate B (zero initial state) ----
        float Bacc = 0.0f;
        if (act) {
            float2 v[TCK];
            #pragma unroll
            for (int u = 0; u < TCK; ++u)
                v[u] = __ldg(in + (size_t)u * F_DIM);
            #pragma unroll
            for (int u = 0; u < TCK; ++u) {
                float m2 = fmaf(v[u].x, v[u].x, v[u].y * v[u].y);
                m2 = fmaxf(m2, 1e-14f);
                float m;
                asm("sqrt.approx.f32 %0, %1;" : "=f"(m) : "f"(m2));
                Bacc = fmaf(ALPHA_F, Bacc, BETA_F * m);
            }
        }
        Bs[chunk][lane] = Bacc;
        __syncthreads();

        // ---- Phase 2: compose chunk start-states (warp 0) ----
        if (tid < 32) {
            float s = scarry;
            #pragma unroll
            for (int c = 0; c < CH; ++c) {
                Ss[c][lane] = s;
                s = fmaf(A, s, Bs[c][lane]);
            }
            scarry = s;   // state entering next segment
        }
        __syncthreads();

        // ---- Phase 3: replay chunk from known start state (reads hit L2) ----
        if (act) {
            float s = Ss[chunk][lane];
            float2* __restrict__ o = out + base;
            float2 v[TCK];
            #pragma unroll
            for (int u = 0; u < TCK; ++u)
                v[u] = __ldg(in + (size_t)u * F_DIM);
            #pragma unroll
            for (int u = 0; u < TCK; ++u) {
                float m2 = fmaf(v[u].x, v[u].x, v[u].y * v[u].y);
                m2 = fmaxf(m2, 1e-14f);
                float m;
                asm("sqrt.approx.f32 %0, %1;" : "=f"(m) : "f"(m2));
                s = fmaf(ALPHA_F, s, BETA_F * m);
                float r;
                asm("rsqrt.approx.f32 %0, %1;" : "=f"(r) : "f"(s));
                float2 w;
                w.x = v[u].x * r;
                w.y = v[u].y * r;
                o[(size_t)u * F_DIM] = w;
            }
        }
        // No extra barrier needed: next phase-1 write to Bs[chunk][lane] only
        // lands after that thread passes the phase-2 barrier of this segment,
        // and warp 0 already consumed Bs before that barrier.
    }
}

extern "C" void kernel_launch(void* const* d_in, const int* in_sizes, int n_in,
                              void* d_out, int out_size) {
    const float2* x = (const float2*)d_in[0];          // [16,1,2000,481,2] fp32
    const float*  init_state = (const float*)d_in[1];  // [1,1,481,1] fp32
    float2* out = (float2*)d_out;

    dim3 block(256);
    dim3 grid(B_DIM * 16);   // 256 blocks: 16 b x 16 f-tiles
    eun_kernel<<<grid, block>>>(x, init_state, out);
}

// round 5
// speedup vs baseline: 2.2102x; 1.1337x over previous
#include <cuda_runtime.h>

// ExponentialUnitNorm, exact segmented chunked linear-scan, register-resident replay.
// x: [B=16, C=1, T=2000, F=481, 2] fp32.
// s_t = 0.01*m_t + 0.99*s_{t-1}. Within a chunk (len TCK) started from 0,
// partial prefixes p_u satisfy  s_u = 0.99^(u+1) * s_in + p_u,
// so after composing chunk start-states in smem, the output pass is a fully
// parallel rescale from registers: no reload, no re-sqrt, no serial chain.
//
// Block: 512 threads = 32 f-lanes x 16 chunk-warps. Grid: 16 b x 16 f-tiles = 256.
// Chip-wide warps: 4096 (~27/SM).

#define B_DIM 16
#define T_DIM 2000
#define F_DIM 481
#define CH    16
#define TCK   5
#define SEG   (CH * TCK)       // 80
#define NSEG  (T_DIM / SEG)    // 25
#define AL 0.99f
#define BE 0.01f

__global__ __launch_bounds__(512, 2)
void eun_kernel(const float2* __restrict__ x,
                const float* __restrict__ init_state,
                float2* __restrict__ out) {
    __shared__ float Bs[CH][32];
    __shared__ float Ss[CH][32];

    const int tid   = threadIdx.x;
    const int lane  = tid & 31;
    const int chunk = tid >> 5;              // 0..15
    const int ftile = blockIdx.x & 15;
    const int b     = blockIdx.x >> 4;
    const int f     = ftile * 32 + lane;
    const bool act  = (f < F_DIM);

    // 0.99^(u+1), u = 0..4 (compile-time literals; double-rounded)
    const float POW[TCK] = {0.99f, 0.9801f, 0.970299f, 0.96059601f, 0.95099005f};
    const float A = 0.95099005f;             // 0.99^TCK

    float scarry = 0.0f;
    if (tid < 32 && act) scarry = init_state[f];

    const float2* __restrict__ xin = x   + ((size_t)b * T_DIM + chunk * TCK) * F_DIM + f;
    float2* __restrict__       o   = out + ((size_t)b * T_DIM + chunk * TCK) * F_DIM + f;
    const size_t segstride = (size_t)SEG * F_DIM;

    #pragma unroll 1
    for (int seg = 0; seg < NSEG; ++seg) {
        float2 v[TCK];
        float  p[TCK];
        float  pc = 0.0f;

        // ---- Phase 1: load + per-chunk prefix (from zero state) ----
        if (act) {
            #pragma unroll
            for (int u = 0; u < TCK; ++u)
                v[u] = __ldg(xin + (size_t)u * F_DIM);
            #pragma unroll
            for (int u = 0; u < TCK; ++u) {
                float m2 = fmaf(v[u].x, v[u].x, v[u].y * v[u].y);
                m2 = fmaxf(m2, 1e-14f);
                float m;
                asm("sqrt.approx.f32 %0, %1;" : "=f"(m) : "f"(m2));
                pc = fmaf(AL, pc, BE * m);
                p[u] = pc;
            }
        }
        Bs[chunk][lane] = pc;                // 0 for inactive lanes
        __syncthreads();

        // ---- Phase 2: compose chunk start-states (warp 0) ----
        if (tid < 32) {
            float s = scarry;
            #pragma unroll
            for (int c = 0; c < CH; ++c) {
                Ss[c][lane] = s;
                s = fmaf(A, s, Bs[c][lane]);
            }
            scarry = s;                      // state entering next segment
        }
        __syncthreads();

        // ---- Phase 3: parallel rescale from registers ----
        if (act) {
            const float s0 = Ss[chunk][lane];
            #pragma unroll
            for (int u = 0; u < TCK; ++u) {
                float st = fmaf(POW[u], s0, p[u]);
                float r;
                asm("rsqrt.approx.f32 %0, %1;" : "=f"(r) : "f"(st));
                float2 w;
                w.x = v[u].x * r;
                w.y = v[u].y * r;
                o[(size_t)u * F_DIM] = w;
            }
        }
        xin += segstride;
        o   += segstride;
    }
}

extern "C" void kernel_launch(void* const* d_in, const int* in_sizes, int n_in,
                              void* d_out, int out_size) {
    const float2* x = (const float2*)d_in[0];          // [16,1,2000,481,2] fp32
    const float*  init_state = (const float*)d_in[1];  // [1,1,481,1] fp32
    float2* out = (float2*)d_out;

    dim3 block(512);
    dim3 grid(B_DIM * 16);   // 256 blocks: 16 b x 16 f-tiles
    eun_kernel<<<grid, block>>>(x, init_state, out);
}

// round 6
// speedup vs baseline: 2.8548x; 1.2917x over previous
#include <cuda_runtime.h>

// ExponentialUnitNorm: exact segmented chunked linear-scan, register-resident,
// software-pipelined loads, single barrier per segment (double-buffered Bs,
// per-warp redundant compose).
// x: [B=16, C=1, T=2000, F=481, 2] fp32.
// s_t = 0.01*m_t + 0.99*s_{t-1}; out = x/sqrt(s).
// Chunk of length TCK from zero state: s_u = 0.99^(u+1)*s_in + p_u.
//
// Block: 512 threads = 32 f-lanes x 16 chunk-warps. Grid: 16 b x 16 f-tiles = 256.

#define B_DIM 16
#define T_DIM 2000
#define F_DIM 481
#define CH    16
#define TCK   5
#define SEG   (CH * TCK)       // 80
#define NSEG  (T_DIM / SEG)    // 25
#define AL 0.99f
#define BE 0.01f

__global__ __launch_bounds__(512, 2)
void eun_kernel(const float2* __restrict__ x,
                const float* __restrict__ init_state,
                float2* __restrict__ out) {
    __shared__ float Bs[2][CH][32];

    const int tid   = threadIdx.x;
    const int lane  = tid & 31;
    const int chunk = tid >> 5;              // 0..15
    const int ftile = blockIdx.x & 15;
    const int b     = blockIdx.x >> 4;
    const int f     = ftile * 32 + lane;
    const bool act  = (f < F_DIM);

    // 0.99^(u+1), u = 0..4
    const float POW[TCK] = {0.99f, 0.9801f, 0.970299f, 0.96059601f, 0.95099005f};
    const float A = 0.95099005f;             // 0.99^TCK

    // Every warp redundantly carries the segment-carry state for its f-lane.
    float scarry = act ? init_state[f] : 0.0f;

    const float2* __restrict__ xin = x   + ((size_t)b * T_DIM + chunk * TCK) * F_DIM + f;
    float2* __restrict__       o   = out + ((size_t)b * T_DIM + chunk * TCK) * F_DIM + f;
    const size_t segstride = (size_t)SEG * F_DIM;

    // Prologue: load segment 0.
    float2 v[TCK];
    if (act) {
        #pragma unroll
        for (int u = 0; u < TCK; ++u)
            v[u] = __ldg(xin + (size_t)u * F_DIM);
    }

    #pragma unroll 1
    for (int seg = 0; seg < NSEG; ++seg) {
        const int par = seg & 1;

        // ---- prefix within chunk (from zero state) ----
        float p[TCK];
        float pc = 0.0f;
        if (act) {
            #pragma unroll
            for (int u = 0; u < TCK; ++u) {
                float m2 = fmaf(v[u].x, v[u].x, v[u].y * v[u].y);
                m2 = fmaxf(m2, 1e-14f);
                float m;
                asm("sqrt.approx.f32 %0, %1;" : "=f"(m) : "f"(m2));
                pc = fmaf(AL, pc, BE * m);
                p[u] = pc;
            }
        }
        Bs[par][chunk][lane] = pc;

        // ---- prefetch next segment BEFORE the barrier (latency overlap) ----
        float2 vn[TCK];
        if (act && seg + 1 < NSEG) {
            const float2* __restrict__ nin = xin + segstride;
            #pragma unroll
            for (int u = 0; u < TCK; ++u)
                vn[u] = __ldg(nin + (size_t)u * F_DIM);
        }

        __syncthreads();

        // ---- per-warp redundant compose over all CH chunks ----
        float s = scarry;
        float mystart = s;
        #pragma unroll
        for (int c = 0; c < CH; ++c) {
            if (c == chunk) mystart = s;     // state entering my chunk
            s = fmaf(A, s, Bs[par][c][lane]);
        }
        scarry = s;                          // state entering next segment

        // ---- parallel rescale + store from registers ----
        if (act) {
            #pragma unroll
            for (int u = 0; u < TCK; ++u) {
                float st = fmaf(POW[u], mystart, p[u]);
                float r;
                asm("rsqrt.approx.f32 %0, %1;" : "=f"(r) : "f"(st));
                float2 w;
                w.x = v[u].x * r;
                w.y = v[u].y * r;
                o[(size_t)u * F_DIM] = w;
            }
            #pragma unroll
            for (int u = 0; u < TCK; ++u)
                v[u] = vn[u];
        }
        xin += segstride;
        o   += segstride;
    }
}

extern "C" void kernel_launch(void* const* d_in, const int* in_sizes, int n_in,
                              void* d_out, int out_size) {
    const float2* x = (const float2*)d_in[0];          // [16,1,2000,481,2] fp32
    const float*  init_state = (const float*)d_in[1];  // [1,1,481,1] fp32
    float2* out = (float2*)d_out;

    dim3 block(512);
    dim3 grid(B_DIM * 16);   // 256 blocks: 16 b x 16 f-tiles
    eun_kernel<<<grid, block>>>(x, init_state, out);
}

// round 7
// speedup vs baseline: 2.9831x; 1.0449x over previous
#include <cuda_runtime.h>

// ExponentialUnitNorm: exact segmented chunked linear-scan, register-resident,
// software-pipelined loads, single barrier per segment, TCK=8 main segments.
// x: [B=16, C=1, T=2000, F=481, 2] fp32.
// s_t = 0.01*m_t + 0.99*s_{t-1}; out = x/sqrt(s).
// Chunk of length L from zero state: s_u = 0.99^(u+1)*s_in + p_u; A_L = 0.99^L.
// T = 15 segments * (16 chunks * 8) + 1 segment * (16 chunks * 5) = 1920 + 80.
//
// Block: 512 threads = 32 f-lanes x 16 chunk-warps. Grid: 16 b x 16 f-tiles = 256
// (all co-resident: 2 blocks/SM x 148 SMs = 296).

#define B_DIM 16
#define T_DIM 2000
#define F_DIM 481
#define CH    16
#define NSEG8 15
#define AL 0.99f
#define BE 0.01f

__global__ __launch_bounds__(512, 2)
void eun_kernel(const float2* __restrict__ x,
                const float* __restrict__ init_state,
                float2* __restrict__ out) {
    __shared__ float Bs[2][CH][32];

    const int tid   = threadIdx.x;
    const int lane  = tid & 31;
    const int chunk = tid >> 5;              // 0..15
    const int ftile = blockIdx.x & 15;
    const int b     = blockIdx.x >> 4;
    const int f     = ftile * 32 + lane;
    const bool act  = (f < F_DIM);

    // 0.99^(u+1), u = 0..7
    const float POW[8] = {0.99f, 0.9801f, 0.970299f, 0.96059601f,
                          0.95099005f, 0.94148015f, 0.93206535f, 0.92274469f};
    const float A8 = 0.92274469f;            // 0.99^8
    const float A5 = 0.95099005f;            // 0.99^5

    float scarry = act ? init_state[f] : 0.0f;

    const float2* __restrict__ xbase = x   + (size_t)b * T_DIM * F_DIM + f;
    float2* __restrict__       obase = out + (size_t)b * T_DIM * F_DIM + f;

    float2 v[8], vn[8];

    // Prologue: load segment 0 (TCK=8).
    if (act) {
        const int off = chunk * 8 * F_DIM;
        #pragma unroll
        for (int u = 0; u < 8; ++u)
            v[u] = __ldg(xbase + off + u * F_DIM);
    }

    #pragma unroll 1
    for (int seg = 0; seg < NSEG8; ++seg) {
        const int par   = seg & 1;
        const int start = seg * (CH * 8);

        // ---- prefix within chunk (zero initial state) ----
        float p[8];
        float pc = 0.0f;
        if (act) {
            #pragma unroll
            for (int u = 0; u < 8; ++u) {
                float m2 = fmaf(v[u].x, v[u].x, v[u].y * v[u].y);
                m2 = fmaxf(m2, 1e-14f);
                float m;
                asm("sqrt.approx.f32 %0, %1;" : "=f"(m) : "f"(m2));
                pc = fmaf(AL, pc, BE * m);
                p[u] = pc;
            }
        }
        Bs[par][chunk][lane] = pc;

        // ---- prefetch next segment BEFORE barrier (latency overlap) ----
        if (act) {
            if (seg < NSEG8 - 1) {
                const int noff = (start + CH * 8 + chunk * 8) * F_DIM;
                #pragma unroll
                for (int u = 0; u < 8; ++u)
                    vn[u] = __ldg(xbase + noff + u * F_DIM);
            } else {
                const int noff = (NSEG8 * CH * 8 + chunk * 5) * F_DIM;
                #pragma unroll
                for (int u = 0; u < 5; ++u)
                    vn[u] = __ldg(xbase + noff + u * F_DIM);
            }
        }

        __syncthreads();

        // ---- per-warp redundant compose over all CH chunks ----
        float s = scarry;
        float mystart = s;
        #pragma unroll
        for (int c = 0; c < CH; ++c) {
            if (c == chunk) mystart = s;
            s = fmaf(A8, s, Bs[par][c][lane]);
        }
        scarry = s;

        // ---- parallel rescale + store from registers ----
        if (act) {
            const int ooff = (start + chunk * 8) * F_DIM;
            #pragma unroll
            for (int u = 0; u < 8; ++u) {
                float st = fmaf(POW[u], mystart, p[u]);
                float r;
                asm("rsqrt.approx.f32 %0, %1;" : "=f"(r) : "f"(st));
                float2 w;
                w.x = v[u].x * r;
                w.y = v[u].y * r;
                obase[ooff + u * F_DIM] = w;
            }
            #pragma unroll
            for (int u = 0; u < 8; ++u)
                v[u] = vn[u];
        }
    }

    // ---- tail segment: TCK=5 (t in [1920, 2000)) ----
    {
        const int start = NSEG8 * CH * 8;    // 1920
        float p[5];
        float pc = 0.0f;
        if (act) {
            #pragma unroll
            for (int u = 0; u < 5; ++u) {
                float m2 = fmaf(v[u].x, v[u].x, v[u].y * v[u].y);
                m2 = fmaxf(m2, 1e-14f);
                float m;
                asm("sqrt.approx.f32 %0, %1;" : "=f"(m) : "f"(m2));
                pc = fmaf(AL, pc, BE * m);
                p[u] = pc;
            }
        }
        Bs[1][chunk][lane] = pc;             // parity 1: safe, see analysis
        __syncthreads();

        float s = scarry;
        float mystart = s;
        #pragma unroll
        for (int c = 0; c < CH; ++c) {
            if (c == chunk) mystart = s;
            s = fmaf(A5, s, Bs[1][c][lane]);
        }

        if (act) {
            const int ooff = (start + chunk * 5) * F_DIM;
            #pragma unroll
            for (int u = 0; u < 5; ++u) {
                float st = fmaf(POW[u], mystart, p[u]);
                float r;
                asm("rsqrt.approx.f32 %0, %1;" : "=f"(r) : "f"(st));
                float2 w;
                w.x = v[u].x * r;
                w.y = v[u].y * r;
                obase[ooff + u * F_DIM] = w;
            }
        }
    }
}

extern "C" void kernel_launch(void* const* d_in, const int* in_sizes, int n_in,
                              void* d_out, int out_size) {
    const float2* x = (const float2*)d_in[0];          // [16,1,2000,481,2] fp32
    const float*  init_state = (const float*)d_in[1];  // [1,1,481,1] fp32
    float2* out = (float2*)d_out;

    dim3 block(512);
    dim3 grid(B_DIM * 16);   // 256 blocks: 16 b x 16 f-tiles
    eun_kernel<<<grid, block>>>(x, init_state, out);
}